// round 6
// baseline (speedup 1.0000x reference)
#include <cuda_runtime.h>
#include <cuda_bf16.h>
#include <math.h>
#include <stdint.h>

#define ROWS      32768
#define CCH       1024
#define NB        8
#define BLKW      128
#define KPAD      136            // padded halves per smem row (272 B)
#define LAMBDA_F  0.01f
#define INV_SQRTC (1.0f / 32.0f)

// ------------------------- scratch (device globals) -------------------------
__device__ __align__(128) __nv_bfloat16 g_xr [(size_t)NB * ROWS * BLKW]; // blocked [blk][row][128]
__device__ __align__(128) __nv_bfloat16 g_xi [(size_t)NB * ROWS * BLKW];
__device__ __align__(128) __nv_bfloat16 g_o1r[(size_t)NB * ROWS * BLKW];
__device__ __align__(128) __nv_bfloat16 g_o1i[(size_t)NB * ROWS * BLKW];
__device__ __align__(128) __nv_bfloat16 g_w1r[NB * BLKW * BLKW];
__device__ __align__(128) __nv_bfloat16 g_w1i[NB * BLKW * BLKW];
__device__ __align__(128) __nv_bfloat16 g_w2r[NB * BLKW * BLKW];
__device__ __align__(128) __nv_bfloat16 g_w2i[NB * BLKW * BLKW];
__device__ float g_gtwr[CCH];
__device__ float g_gtwi[CCH];

// ------------------------- setup kernels -------------------------------------
__global__ void setup_twiddles(float* twr, float* twi) {
    int i = blockIdx.x * blockDim.x + threadIdx.x;
    if (i < CCH) {
        float s, c;
        sincosf(-6.283185307179586f * (float)i / (float)CCH, &s, &c);
        twr[i] = c; twi[i] = s;
    }
}

__global__ void convert_weights(const float* __restrict__ w1,
                                const float* __restrict__ w2,
                                __nv_bfloat16* __restrict__ W1r, __nv_bfloat16* __restrict__ W1i,
                                __nv_bfloat16* __restrict__ W2r, __nv_bfloat16* __restrict__ W2i) {
    int idx = blockIdx.x * blockDim.x + threadIdx.x;   // dst layout [blk][n][k]
    if (idx >= NB * BLKW * BLKW) return;
    int blk = idx >> 14;
    int n   = (idx >> 7) & 127;
    int k   = idx & 127;
    size_t src = (size_t)blk * (BLKW * BLKW) + (size_t)k * BLKW + n;  // w[.][blk][k][n]
    W1r[idx] = __float2bfloat16(w1[src]);
    W1i[idx] = __float2bfloat16(w1[(size_t)NB * BLKW * BLKW + src]);
    W2r[idx] = __float2bfloat16(w2[src]);
    W2i[idx] = __float2bfloat16(w2[(size_t)NB * BLKW * BLKW + src]);
}

// ------------------------- radix-4 Stockham FFT (1 sync/stage) ----------------
// forward: two real rows packed into one complex FFT
__global__ __launch_bounds__(256) void fft_fwd_kernel(const float* __restrict__ x,
                                                      __nv_bfloat16* __restrict__ outr,
                                                      __nv_bfloat16* __restrict__ outi,
                                                      const float* __restrict__ gtwr,
                                                      const float* __restrict__ gtwi) {
    __shared__ float ar[CCH], ai[CCH], br[CCH], bi[CCH];
    __shared__ float twr[CCH], twi[CCH];
    const int t = threadIdx.x;
    const size_t rowa = (size_t)blockIdx.x * 2;
    const float* xa = x + rowa * CCH;
    const float* xb = xa + CCH;

    #pragma unroll
    for (int q = 0; q < 4; q++) {
        int pos = t + 256 * q;
        ar[pos] = xa[pos];
        ai[pos] = xb[pos];
        twr[pos] = gtwr[pos];
        twi[pos] = gtwi[pos];
    }
    __syncthreads();

    float *pr = ar, *pi = ai, *qr = br, *qi = bi;
    #pragma unroll
    for (int p = 1; p <= 256; p <<= 2) {
        const int k = t & (p - 1);
        const int j = ((t - k) << 2) + k;
        const int a1 = k * (256 / p);
        float u0r = pr[t],       u0i = pi[t];
        float x1r = pr[t + 256], x1i = pi[t + 256];
        float x2r = pr[t + 512], x2i = pi[t + 512];
        float x3r = pr[t + 768], x3i = pi[t + 768];
        float w1r = twr[a1],     w1i = twi[a1];
        float w2r = twr[2 * a1], w2i = twi[2 * a1];
        float w3r = twr[3 * a1], w3i = twi[3 * a1];
        float u1r = x1r * w1r - x1i * w1i, u1i = x1r * w1i + x1i * w1r;
        float u2r = x2r * w2r - x2i * w2i, u2i = x2r * w2i + x2i * w2r;
        float u3r = x3r * w3r - x3i * w3i, u3i = x3r * w3i + x3i * w3r;
        float v0r = u0r + u2r, v0i = u0i + u2i;
        float v1r = u0r - u2r, v1i = u0i - u2i;
        float v2r = u1r + u3r, v2i = u1i + u3i;
        float v3r = u1i - u3i, v3i = u3r - u1r;   // -i*(u1-u3)
        qr[j]         = v0r + v2r;  qi[j]         = v0i + v2i;
        qr[j + p]     = v1r + v3r;  qi[j + p]     = v1i + v3i;
        qr[j + 2 * p] = v0r - v2r;  qi[j + 2 * p] = v0i - v2i;
        qr[j + 3 * p] = v1r - v3r;  qi[j + 3 * p] = v1i - v3i;
        __syncthreads();
        float* tp;
        tp = pr; pr = qr; qr = tp;
        tp = pi; pi = qi; qi = tp;
    }

    // unpack: A=(Z[k]+conj(Z[-k]))/2, B=(Z[k]-conj(Z[-k]))/2i ; fold ortho scale
    const float HS = 0.5f * INV_SQRTC;
    #pragma unroll
    for (int q = 0; q < 4; q++) {
        int pos = t + 256 * q;
        int nk = (CCH - pos) & (CCH - 1);
        float zr = pr[pos], zi = pi[pos];
        float wr = pr[nk],  wi = pi[nk];
        float Ar = HS * (zr + wr), Ai = HS * (zi - wi);
        float Br = HS * (zi + wi), Bi = HS * (wr - zr);
        int blk = pos >> 7, col = pos & 127;
        size_t ga = ((size_t)blk * ROWS + rowa) * BLKW + col;
        outr[ga] = __float2bfloat16(Ar);
        outi[ga] = __float2bfloat16(Ai);
        outr[ga + BLKW] = __float2bfloat16(Br);
        outi[ga + BLKW] = __float2bfloat16(Bi);
    }
}

// inverse: Hermitian-symmetrize two spectra, pack, one IFFT -> two real rows
__global__ __launch_bounds__(256) void fft_inv_kernel(const __nv_bfloat16* __restrict__ inr,
                                                      const __nv_bfloat16* __restrict__ ini,
                                                      const float* __restrict__ xres,
                                                      float* __restrict__ out,
                                                      const float* __restrict__ gtwr,
                                                      const float* __restrict__ gtwi) {
    __shared__ float yar[CCH], yai[CCH], ybr[CCH], ybi[CCH];
    __shared__ float ar[CCH], ai[CCH];
    __shared__ float twr[CCH], twi[CCH];
    const int t = threadIdx.x;
    const size_t rowa = (size_t)blockIdx.x * 2;

    #pragma unroll
    for (int q = 0; q < 4; q++) {
        int pos = t + 256 * q;
        int blk = pos >> 7, col = pos & 127;
        size_t ga = ((size_t)blk * ROWS + rowa) * BLKW + col;
        yar[pos] = __bfloat162float(inr[ga]);
        yai[pos] = __bfloat162float(ini[ga]);
        ybr[pos] = __bfloat162float(inr[ga + BLKW]);
        ybi[pos] = __bfloat162float(ini[ga + BLKW]);
        twr[pos] = gtwr[pos];
        twi[pos] = gtwi[pos];
    }
    __syncthreads();

    // A = Herm(Ya), B = Herm(Yb); z_in = A + iB ; fold ortho scale
    const float HS = 0.5f * INV_SQRTC;
    #pragma unroll
    for (int q = 0; q < 4; q++) {
        int pos = t + 256 * q;
        int nk = (CCH - pos) & (CCH - 1);
        float Ar = HS * (yar[pos] + yar[nk]);
        float Ai = HS * (yai[pos] - yai[nk]);
        float Br = HS * (ybr[pos] + ybr[nk]);
        float Bi = HS * (ybi[pos] - ybi[nk]);
        ar[pos] = Ar - Bi;
        ai[pos] = Ai + Br;
    }
    __syncthreads();

    float *pr = ar, *pi = ai, *qr = yar, *qi = yai;
    #pragma unroll
    for (int p = 1; p <= 256; p <<= 2) {
        const int k = t & (p - 1);
        const int j = ((t - k) << 2) + k;
        const int a1 = k * (256 / p);
        float u0r = pr[t],       u0i = pi[t];
        float x1r = pr[t + 256], x1i = pi[t + 256];
        float x2r = pr[t + 512], x2i = pi[t + 512];
        float x3r = pr[t + 768], x3i = pi[t + 768];
        float w1r = twr[a1],     w1i = -twi[a1];
        float w2r = twr[2 * a1], w2i = -twi[2 * a1];
        float w3r = twr[3 * a1], w3i = -twi[3 * a1];
        float u1r = x1r * w1r - x1i * w1i, u1i = x1r * w1i + x1i * w1r;
        float u2r = x2r * w2r - x2i * w2i, u2i = x2r * w2i + x2i * w2r;
        float u3r = x3r * w3r - x3i * w3i, u3i = x3r * w3i + x3i * w3r;
        float v0r = u0r + u2r, v0i = u0i + u2i;
        float v1r = u0r - u2r, v1i = u0i - u2i;
        float v2r = u1r + u3r, v2i = u1i + u3i;
        float v3r = u3i - u1i, v3i = u1r - u3r;   // +i*(u1-u3)
        qr[j]         = v0r + v2r;  qi[j]         = v0i + v2i;
        qr[j + p]     = v1r + v3r;  qi[j + p]     = v1i + v3i;
        qr[j + 2 * p] = v0r - v2r;  qi[j + 2 * p] = v0i - v2i;
        qr[j + 3 * p] = v1r - v3r;  qi[j + 3 * p] = v1i - v3i;
        __syncthreads();
        float* tp;
        tp = pr; pr = qr; qr = tp;
        tp = pi; pi = qi; qi = tp;
    }

    #pragma unroll
    for (int q = 0; q < 4; q++) {
        int pos = t + 256 * q;
        size_t ga = rowa * CCH + pos;
        out[ga]       = pr[pos] + xres[ga];
        out[ga + CCH] = pi[pos] + xres[ga + CCH];
    }
}

// ------------------------- HMMA MLP layer (Gauss 3-mult) ----------------------
__device__ __forceinline__ float softshrink_f(float v) {
    return (v > LAMBDA_F) ? (v - LAMBDA_F) : ((v < -LAMBDA_F) ? (v + LAMBDA_F) : 0.0f);
}
__device__ __forceinline__ uint32_t smem_u32(const void* p) {
    uint32_t a;
    asm("{ .reg .u64 t; cvta.to.shared.u64 t, %1; cvt.u32.u64 %0, t; }" : "=r"(a) : "l"(p));
    return a;
}
__device__ __forceinline__ void mma16816(float* d, const uint32_t* a, const uint32_t* b) {
    asm volatile(
        "mma.sync.aligned.m16n8k16.row.col.f32.bf16.bf16.f32 "
        "{%0,%1,%2,%3}, {%4,%5,%6,%7}, {%8,%9}, {%0,%1,%2,%3};"
        : "+f"(d[0]), "+f"(d[1]), "+f"(d[2]), "+f"(d[3])
        : "r"(a[0]), "r"(a[1]), "r"(a[2]), "r"(a[3]), "r"(b[0]), "r"(b[1]));
}
__device__ __forceinline__ void ldm_x4(uint32_t* r, uint32_t addr) {
    asm volatile("ldmatrix.sync.aligned.m8n8.x4.shared.b16 {%0,%1,%2,%3}, [%4];"
        : "=r"(r[0]), "=r"(r[1]), "=r"(r[2]), "=r"(r[3]) : "r"(addr));
}
__device__ __forceinline__ void ldm_x2(uint32_t* r, uint32_t addr) {
    asm volatile("ldmatrix.sync.aligned.m8n8.x2.shared.b16 {%0,%1}, [%2];"
        : "=r"(r[0]), "=r"(r[1]) : "r"(addr));
}
__device__ __forceinline__ uint32_t badd2(uint32_t a, uint32_t b) {
    uint32_t d;
    asm("add.rn.bf16x2 %0, %1, %2;" : "=r"(d) : "r"(a), "r"(b));
    return d;
}

// grid (ROWS/64, NB), 256 threads (8 warps), 2 CTAs/SM.
#define SM_X_H    (64 * KPAD)
#define SM_W_H    (128 * KPAD)
#define SM_BYTES  ((2 * SM_X_H + 2 * SM_W_H) * 2 + 2 * 128 * 4)

template <bool RELU, bool SHRINK>
__global__ __launch_bounds__(256, 2) void mma_mlp_kernel(
        const __nv_bfloat16* __restrict__ Xr, const __nv_bfloat16* __restrict__ Xi,
        const __nv_bfloat16* __restrict__ Wr, const __nv_bfloat16* __restrict__ Wi,
        const float* __restrict__ Bg,
        __nv_bfloat16* __restrict__ Or, __nv_bfloat16* __restrict__ Oi) {
    extern __shared__ __nv_bfloat16 sm[];
    __nv_bfloat16* sXr = sm;
    __nv_bfloat16* sXi = sXr + SM_X_H;
    __nv_bfloat16* sWr = sXi + SM_X_H;
    __nv_bfloat16* sWi = sWr + SM_W_H;
    float* sBr = (float*)(sWi + SM_W_H);
    float* sBi = sBr + 128;

    const int tid  = threadIdx.x;
    const int lane = tid & 31;
    const int wid  = tid >> 5;
    const int blk  = blockIdx.y;
    const int m0   = blockIdx.x * 64;

    // ---- stage tiles ----
    const __nv_bfloat16* gXr = Xr + ((size_t)blk * ROWS + m0) * BLKW;
    const __nv_bfloat16* gXi = Xi + ((size_t)blk * ROWS + m0) * BLKW;
    const __nv_bfloat16* gWr = Wr + (size_t)blk * BLKW * BLKW;
    const __nv_bfloat16* gWi = Wi + (size_t)blk * BLKW * BLKW;
    #pragma unroll
    for (int it = 0; it < 4; it++) {
        int idx = tid + it * 256;
        int row = idx >> 4, c = idx & 15;
        *(uint4*)(sXr + row * KPAD + c * 8) = *(const uint4*)(gXr + row * BLKW + c * 8);
        *(uint4*)(sXi + row * KPAD + c * 8) = *(const uint4*)(gXi + row * BLKW + c * 8);
    }
    #pragma unroll
    for (int it = 0; it < 8; it++) {
        int idx = tid + it * 256;
        int row = idx >> 4, c = idx & 15;
        *(uint4*)(sWr + row * KPAD + c * 8) = *(const uint4*)(gWr + row * BLKW + c * 8);
        *(uint4*)(sWi + row * KPAD + c * 8) = *(const uint4*)(gWi + row * BLKW + c * 8);
    }
    if (tid < BLKW) {
        sBr[tid] = Bg[blk * BLKW + tid];
        sBi[tid] = Bg[NB * BLKW + blk * BLKW + tid];
    }
    __syncthreads();

    const int wm = wid & 3;      // 16-row group
    const int wn = wid >> 2;     // 64-col group

    const int grp = lane >> 3;
    const int rA  = wm * 16 + (lane & 7) + ((grp & 1) << 3);
    const int kA  = (grp >> 1) << 3;
    const uint32_t offA = (uint32_t)(rA * KPAD + kA) * 2;
    const uint32_t offB = (uint32_t)((lane & 7) * KPAD + ((lane >> 3) & 1) * 8) * 2;
    const uint32_t baseXr = smem_u32(sXr), baseXi = smem_u32(sXi);
    const uint32_t baseWr = smem_u32(sWr), baseWi = smem_u32(sWi);

    #pragma unroll
    for (int pass = 0; pass < 2; pass++) {
        const int n_base = wn * 64 + pass * 32;

        // Gauss accumulators: t1 = Xr*Wr, t2 = Xi*Wi, t3 = (Xr+Xi)*(Wr+Wi)
        float t1[4][4], t2[4][4], t3[4][4];
        #pragma unroll
        for (int ni = 0; ni < 4; ni++)
            #pragma unroll
            for (int q = 0; q < 4; q++) { t1[ni][q] = 0.0f; t2[ni][q] = 0.0f; t3[ni][q] = 0.0f; }

        #pragma unroll
        for (int ks = 0; ks < 8; ks++) {
            const uint32_t kb = (uint32_t)(ks * 16) * 2;
            uint32_t axr[4], axi[4], axs[4];
            ldm_x4(axr, baseXr + offA + kb);
            ldm_x4(axi, baseXi + offA + kb);
            #pragma unroll
            for (int q = 0; q < 4; q++) axs[q] = badd2(axr[q], axi[q]);

            uint32_t bwr[4][2], bwi[4][2], bws[4][2];
            #pragma unroll
            for (int ni = 0; ni < 4; ni++) {
                const uint32_t nb = (uint32_t)((n_base + ni * 8) * KPAD) * 2;
                ldm_x2(bwr[ni], baseWr + nb + offB + kb);
                ldm_x2(bwi[ni], baseWi + nb + offB + kb);
                bws[ni][0] = badd2(bwr[ni][0], bwi[ni][0]);
                bws[ni][1] = badd2(bwr[ni][1], bwi[ni][1]);
            }
            #pragma unroll
            for (int ni = 0; ni < 4; ni++) {
                mma16816(t1[ni], axr, bwr[ni]);
                mma16816(t2[ni], axi, bwi[ni]);
                mma16816(t3[ni], axs, bws[ni]);
            }
        }

        // ---- epilogue: Dr = t1 - t2, Di = t3 - t1 - t2 ----
        #pragma unroll
        for (int ni = 0; ni < 4; ni++) {
            const int col = n_base + ni * 8 + (lane & 3) * 2;
            const int row = m0 + wm * 16 + (lane >> 2);
            const float br0 = sBr[col], br1 = sBr[col + 1];
            const float bi0 = sBi[col], bi1 = sBi[col + 1];
            #pragma unroll
            for (int half = 0; half < 2; half++) {
                const int q0 = half * 2, q1 = half * 2 + 1;
                float vr0 = t1[ni][q0] - t2[ni][q0] + br0;
                float vr1 = t1[ni][q1] - t2[ni][q1] + br1;
                float vi0 = t3[ni][q0] - t1[ni][q0] - t2[ni][q0] + bi0;
                float vi1 = t3[ni][q1] - t1[ni][q1] - t2[ni][q1] + bi1;
                if (RELU) {
                    vr0 = fmaxf(vr0, 0.0f); vr1 = fmaxf(vr1, 0.0f);
                    vi0 = fmaxf(vi0, 0.0f); vi1 = fmaxf(vi1, 0.0f);
                }
                if (SHRINK) {
                    vr0 = softshrink_f(vr0); vr1 = softshrink_f(vr1);
                    vi0 = softshrink_f(vi0); vi1 = softshrink_f(vi1);
                }
                __nv_bfloat162 pr2 = __floats2bfloat162_rn(vr0, vr1);
                __nv_bfloat162 pi2 = __floats2bfloat162_rn(vi0, vi1);
                const size_t g = ((size_t)blk * ROWS + row + half * 8) * BLKW + col;
                *(__nv_bfloat162*)(Or + g) = pr2;
                *(__nv_bfloat162*)(Oi + g) = pi2;
            }
        }
    }
}

// -----------------------------------------------------------------------------
extern "C" void kernel_launch(void* const* d_in, const int* in_sizes, int n_in,
                              void* d_out, int out_size) {
    (void)in_sizes; (void)n_in; (void)out_size;
    const float* x  = (const float*)d_in[0];
    const float* w1 = (const float*)d_in[1];
    const float* b1 = (const float*)d_in[2];
    const float* w2 = (const float*)d_in[3];
    const float* b2 = (const float*)d_in[4];
    float* out = (float*)d_out;

    __nv_bfloat16 *xr, *xi, *o1r, *o1i, *w1r, *w1i, *w2r, *w2i;
    float *gtwr, *gtwi;
    cudaGetSymbolAddress((void**)&xr,  g_xr);
    cudaGetSymbolAddress((void**)&xi,  g_xi);
    cudaGetSymbolAddress((void**)&o1r, g_o1r);
    cudaGetSymbolAddress((void**)&o1i, g_o1i);
    cudaGetSymbolAddress((void**)&w1r, g_w1r);
    cudaGetSymbolAddress((void**)&w1i, g_w1i);
    cudaGetSymbolAddress((void**)&w2r, g_w2r);
    cudaGetSymbolAddress((void**)&w2i, g_w2i);
    cudaGetSymbolAddress((void**)&gtwr, g_gtwr);
    cudaGetSymbolAddress((void**)&gtwi, g_gtwi);

    cudaFuncSetAttribute(mma_mlp_kernel<true, false>,
                         cudaFuncAttributeMaxDynamicSharedMemorySize, SM_BYTES);
    cudaFuncSetAttribute(mma_mlp_kernel<false, true>,
                         cudaFuncAttributeMaxDynamicSharedMemorySize, SM_BYTES);

    setup_twiddles<<<4, 256>>>(gtwr, gtwi);
    convert_weights<<<(NB * BLKW * BLKW + 255) / 256, 256>>>(w1, w2, w1r, w1i, w2r, w2i);

    fft_fwd_kernel<<<ROWS / 2, 256>>>(x, xr, xi, gtwr, gtwi);

    dim3 grid(ROWS / 64, NB);
    mma_mlp_kernel<true, false><<<grid, 256, SM_BYTES>>>(xr, xi, w1r, w1i, b1, o1r, o1i);
    mma_mlp_kernel<false, true><<<grid, 256, SM_BYTES>>>(o1r, o1i, w2r, w2i, b2, xr, xi);

    fft_inv_kernel<<<ROWS / 2, 256>>>(xr, xi, x, out, gtwr, gtwi);
}

// round 7
// speedup vs baseline: 1.0583x; 1.0583x over previous
#include <cuda_runtime.h>
#include <cuda_bf16.h>
#include <math.h>
#include <stdint.h>

#define ROWS      32768
#define CCH       1024
#define NB        8
#define BLKW      128
#define KPAD      136            // padded halves per smem row (272 B)
#define LAMBDA_F  0.01f
#define INV_SQRTC (1.0f / 32.0f)

// ------------------------- scratch (device globals) -------------------------
__device__ __align__(128) __nv_bfloat16 g_xr [(size_t)NB * ROWS * BLKW]; // blocked [blk][row][128]
__device__ __align__(128) __nv_bfloat16 g_xi [(size_t)NB * ROWS * BLKW];
__device__ __align__(128) __nv_bfloat16 g_w1r[NB * BLKW * BLKW];
__device__ __align__(128) __nv_bfloat16 g_w1i[NB * BLKW * BLKW];
__device__ __align__(128) __nv_bfloat16 g_w2r[NB * BLKW * BLKW];
__device__ __align__(128) __nv_bfloat16 g_w2i[NB * BLKW * BLKW];
__device__ float g_gtwr[CCH];
__device__ float g_gtwi[CCH];

// ------------------------- setup kernels -------------------------------------
__global__ void setup_twiddles(float* twr, float* twi) {
    int i = blockIdx.x * blockDim.x + threadIdx.x;
    if (i < CCH) {
        float s, c;
        sincosf(-6.283185307179586f * (float)i / (float)CCH, &s, &c);
        twr[i] = c; twi[i] = s;
    }
}

__global__ void convert_weights(const float* __restrict__ w1,
                                const float* __restrict__ w2,
                                __nv_bfloat16* __restrict__ W1r, __nv_bfloat16* __restrict__ W1i,
                                __nv_bfloat16* __restrict__ W2r, __nv_bfloat16* __restrict__ W2i) {
    int idx = blockIdx.x * blockDim.x + threadIdx.x;   // dst layout [blk][n][k]
    if (idx >= NB * BLKW * BLKW) return;
    int blk = idx >> 14;
    int n   = (idx >> 7) & 127;
    int k   = idx & 127;
    size_t src = (size_t)blk * (BLKW * BLKW) + (size_t)k * BLKW + n;  // w[.][blk][k][n]
    W1r[idx] = __float2bfloat16(w1[src]);
    W1i[idx] = __float2bfloat16(w1[(size_t)NB * BLKW * BLKW + src]);
    W2r[idx] = __float2bfloat16(w2[src]);
    W2i[idx] = __float2bfloat16(w2[(size_t)NB * BLKW * BLKW + src]);
}

// ------------------------- radix-4 Stockham FFT (1 sync/stage) ----------------
__global__ __launch_bounds__(256) void fft_fwd_kernel(const float* __restrict__ x,
                                                      __nv_bfloat16* __restrict__ outr,
                                                      __nv_bfloat16* __restrict__ outi,
                                                      const float* __restrict__ gtwr,
                                                      const float* __restrict__ gtwi) {
    __shared__ float ar[CCH], ai[CCH], br[CCH], bi[CCH];
    __shared__ float twr[CCH], twi[CCH];
    const int t = threadIdx.x;
    const size_t rowa = (size_t)blockIdx.x * 2;
    const float* xa = x + rowa * CCH;
    const float* xb = xa + CCH;

    #pragma unroll
    for (int q = 0; q < 4; q++) {
        int pos = t + 256 * q;
        ar[pos] = xa[pos];
        ai[pos] = xb[pos];
        twr[pos] = gtwr[pos];
        twi[pos] = gtwi[pos];
    }
    __syncthreads();

    float *pr = ar, *pi = ai, *qr = br, *qi = bi;
    #pragma unroll
    for (int p = 1; p <= 256; p <<= 2) {
        const int k = t & (p - 1);
        const int j = ((t - k) << 2) + k;
        const int a1 = k * (256 / p);
        float u0r = pr[t],       u0i = pi[t];
        float x1r = pr[t + 256], x1i = pi[t + 256];
        float x2r = pr[t + 512], x2i = pi[t + 512];
        float x3r = pr[t + 768], x3i = pi[t + 768];
        float w1r = twr[a1],     w1i = twi[a1];
        float w2r = twr[2 * a1], w2i = twi[2 * a1];
        float w3r = twr[3 * a1], w3i = twi[3 * a1];
        float u1r = x1r * w1r - x1i * w1i, u1i = x1r * w1i + x1i * w1r;
        float u2r = x2r * w2r - x2i * w2i, u2i = x2r * w2i + x2i * w2r;
        float u3r = x3r * w3r - x3i * w3i, u3i = x3r * w3i + x3i * w3r;
        float v0r = u0r + u2r, v0i = u0i + u2i;
        float v1r = u0r - u2r, v1i = u0i - u2i;
        float v2r = u1r + u3r, v2i = u1i + u3i;
        float v3r = u1i - u3i, v3i = u3r - u1r;   // -i*(u1-u3)
        qr[j]         = v0r + v2r;  qi[j]         = v0i + v2i;
        qr[j + p]     = v1r + v3r;  qi[j + p]     = v1i + v3i;
        qr[j + 2 * p] = v0r - v2r;  qi[j + 2 * p] = v0i - v2i;
        qr[j + 3 * p] = v1r - v3r;  qi[j + 3 * p] = v1i - v3i;
        __syncthreads();
        float* tp;
        tp = pr; pr = qr; qr = tp;
        tp = pi; pi = qi; qi = tp;
    }

    const float HS = 0.5f * INV_SQRTC;
    #pragma unroll
    for (int q = 0; q < 4; q++) {
        int pos = t + 256 * q;
        int nk = (CCH - pos) & (CCH - 1);
        float zr = pr[pos], zi = pi[pos];
        float wr = pr[nk],  wi = pi[nk];
        float Ar = HS * (zr + wr), Ai = HS * (zi - wi);
        float Br = HS * (zi + wi), Bi = HS * (wr - zr);
        int blk = pos >> 7, col = pos & 127;
        size_t ga = ((size_t)blk * ROWS + rowa) * BLKW + col;
        outr[ga] = __float2bfloat16(Ar);
        outi[ga] = __float2bfloat16(Ai);
        outr[ga + BLKW] = __float2bfloat16(Br);
        outi[ga + BLKW] = __float2bfloat16(Bi);
    }
}

__global__ __launch_bounds__(256) void fft_inv_kernel(const __nv_bfloat16* __restrict__ inr,
                                                      const __nv_bfloat16* __restrict__ ini,
                                                      const float* __restrict__ xres,
                                                      float* __restrict__ out,
                                                      const float* __restrict__ gtwr,
                                                      const float* __restrict__ gtwi) {
    __shared__ float yar[CCH], yai[CCH], ybr[CCH], ybi[CCH];
    __shared__ float ar[CCH], ai[CCH];
    __shared__ float twr[CCH], twi[CCH];
    const int t = threadIdx.x;
    const size_t rowa = (size_t)blockIdx.x * 2;

    #pragma unroll
    for (int q = 0; q < 4; q++) {
        int pos = t + 256 * q;
        int blk = pos >> 7, col = pos & 127;
        size_t ga = ((size_t)blk * ROWS + rowa) * BLKW + col;
        yar[pos] = __bfloat162float(inr[ga]);
        yai[pos] = __bfloat162float(ini[ga]);
        ybr[pos] = __bfloat162float(inr[ga + BLKW]);
        ybi[pos] = __bfloat162float(ini[ga + BLKW]);
        twr[pos] = gtwr[pos];
        twi[pos] = gtwi[pos];
    }
    __syncthreads();

    const float HS = 0.5f * INV_SQRTC;
    #pragma unroll
    for (int q = 0; q < 4; q++) {
        int pos = t + 256 * q;
        int nk = (CCH - pos) & (CCH - 1);
        float Ar = HS * (yar[pos] + yar[nk]);
        float Ai = HS * (yai[pos] - yai[nk]);
        float Br = HS * (ybr[pos] + ybr[nk]);
        float Bi = HS * (ybi[pos] - ybi[nk]);
        ar[pos] = Ar - Bi;
        ai[pos] = Ai + Br;
    }
    __syncthreads();

    float *pr = ar, *pi = ai, *qr = yar, *qi = yai;
    #pragma unroll
    for (int p = 1; p <= 256; p <<= 2) {
        const int k = t & (p - 1);
        const int j = ((t - k) << 2) + k;
        const int a1 = k * (256 / p);
        float u0r = pr[t],       u0i = pi[t];
        float x1r = pr[t + 256], x1i = pi[t + 256];
        float x2r = pr[t + 512], x2i = pi[t + 512];
        float x3r = pr[t + 768], x3i = pi[t + 768];
        float w1r = twr[a1],     w1i = -twi[a1];
        float w2r = twr[2 * a1], w2i = -twi[2 * a1];
        float w3r = twr[3 * a1], w3i = -twi[3 * a1];
        float u1r = x1r * w1r - x1i * w1i, u1i = x1r * w1i + x1i * w1r;
        float u2r = x2r * w2r - x2i * w2i, u2i = x2r * w2i + x2i * w2r;
        float u3r = x3r * w3r - x3i * w3i, u3i = x3r * w3i + x3i * w3r;
        float v0r = u0r + u2r, v0i = u0i + u2i;
        float v1r = u0r - u2r, v1i = u0i - u2i;
        float v2r = u1r + u3r, v2i = u1i + u3i;
        float v3r = u3i - u1i, v3i = u1r - u3r;   // +i*(u1-u3)
        qr[j]         = v0r + v2r;  qi[j]         = v0i + v2i;
        qr[j + p]     = v1r + v3r;  qi[j + p]     = v1i + v3i;
        qr[j + 2 * p] = v0r - v2r;  qi[j + 2 * p] = v0i - v2i;
        qr[j + 3 * p] = v1r - v3r;  qi[j + 3 * p] = v1i - v3i;
        __syncthreads();
        float* tp;
        tp = pr; pr = qr; qr = tp;
        tp = pi; pi = qi; qi = tp;
    }

    #pragma unroll
    for (int q = 0; q < 4; q++) {
        int pos = t + 256 * q;
        size_t ga = rowa * CCH + pos;
        out[ga]       = pr[pos] + xres[ga];
        out[ga + CCH] = pi[pos] + xres[ga + CCH];
    }
}

// ------------------------- fused 2-layer HMMA MLP ----------------------------
__device__ __forceinline__ float softshrink_f(float v) {
    return (v > LAMBDA_F) ? (v - LAMBDA_F) : ((v < -LAMBDA_F) ? (v + LAMBDA_F) : 0.0f);
}
__device__ __forceinline__ uint32_t smem_u32(const void* p) {
    uint32_t a;
    asm("{ .reg .u64 t; cvta.to.shared.u64 t, %1; cvt.u32.u64 %0, t; }" : "=r"(a) : "l"(p));
    return a;
}
__device__ __forceinline__ void mma16816(float* d, const uint32_t* a, const uint32_t* b) {
    asm volatile(
        "mma.sync.aligned.m16n8k16.row.col.f32.bf16.bf16.f32 "
        "{%0,%1,%2,%3}, {%4,%5,%6,%7}, {%8,%9}, {%0,%1,%2,%3};"
        : "+f"(d[0]), "+f"(d[1]), "+f"(d[2]), "+f"(d[3])
        : "r"(a[0]), "r"(a[1]), "r"(a[2]), "r"(a[3]), "r"(b[0]), "r"(b[1]));
}
__device__ __forceinline__ void ldm_x4(uint32_t* r, uint32_t addr) {
    asm volatile("ldmatrix.sync.aligned.m8n8.x4.shared.b16 {%0,%1,%2,%3}, [%4];"
        : "=r"(r[0]), "=r"(r[1]), "=r"(r[2]), "=r"(r[3]) : "r"(addr));
}
__device__ __forceinline__ void ldm_x2(uint32_t* r, uint32_t addr) {
    asm volatile("ldmatrix.sync.aligned.m8n8.x2.shared.b16 {%0,%1}, [%2];"
        : "=r"(r[0]), "=r"(r[1]) : "r"(addr));
}

// one complex GEMM layer: A (64xKPAD r/i in smem) x W (128xKPAD r/i) -> 16x32/warp accums
__device__ __forceinline__ void complex_gemm_layer(
        uint32_t baseAr, uint32_t baseAi, uint32_t baseWr, uint32_t baseWi,
        uint32_t offA, uint32_t offB, int n_base,
        float accR[4][4], float accI[4][4]) {
    #pragma unroll
    for (int ni = 0; ni < 4; ni++)
        #pragma unroll
        for (int q = 0; q < 4; q++) { accR[ni][q] = 0.0f; accI[ni][q] = 0.0f; }

    #pragma unroll
    for (int ks = 0; ks < 8; ks++) {
        const uint32_t kb = (uint32_t)(ks * 16) * 2;
        uint32_t axr[4], axi[4], axni[4];
        ldm_x4(axr, baseAr + offA + kb);
        ldm_x4(axi, baseAi + offA + kb);
        #pragma unroll
        for (int q = 0; q < 4; q++) axni[q] = axi[q] ^ 0x80008000u;

        uint32_t bwr[4][2], bwi[4][2];
        #pragma unroll
        for (int ni = 0; ni < 4; ni++) {
            const uint32_t nb = (uint32_t)((n_base + ni * 8) * KPAD) * 2;
            ldm_x2(bwr[ni], baseWr + nb + offB + kb);
            ldm_x2(bwi[ni], baseWi + nb + offB + kb);
        }
        #pragma unroll
        for (int ni = 0; ni < 4; ni++) {
            mma16816(accR[ni], axr,  bwr[ni]);   // + Ar*Wr
            mma16816(accR[ni], axni, bwi[ni]);   // - Ai*Wi
            mma16816(accI[ni], axi,  bwr[ni]);   // + Ai*Wr
            mma16816(accI[ni], axr,  bwi[ni]);   // + Ar*Wi
        }
    }
}

// grid (ROWS/64, NB), 512 threads (16 warps, 4x4), 1 CTA/SM.
#define SM_X_H    (64 * KPAD)
#define SM_W_H    (128 * KPAD)
#define SM_BYTES  ((4 * SM_X_H + 4 * SM_W_H) * 2 + 4 * 128 * 4)

__global__ __launch_bounds__(512, 1) void fused_mlp_kernel(
        const __nv_bfloat16* __restrict__ Xr, const __nv_bfloat16* __restrict__ Xi,
        const __nv_bfloat16* __restrict__ W1r, const __nv_bfloat16* __restrict__ W1i,
        const __nv_bfloat16* __restrict__ W2r, const __nv_bfloat16* __restrict__ W2i,
        const float* __restrict__ B1, const float* __restrict__ B2,
        __nv_bfloat16* __restrict__ Or, __nv_bfloat16* __restrict__ Oi) {
    extern __shared__ __nv_bfloat16 sm[];
    __nv_bfloat16* sXr  = sm;
    __nv_bfloat16* sXi  = sXr + SM_X_H;
    __nv_bfloat16* sO1r = sXi + SM_X_H;
    __nv_bfloat16* sO1i = sO1r + SM_X_H;
    __nv_bfloat16* sW1r = sO1i + SM_X_H;
    __nv_bfloat16* sW1i = sW1r + SM_W_H;
    __nv_bfloat16* sW2r = sW1i + SM_W_H;
    __nv_bfloat16* sW2i = sW2r + SM_W_H;
    float* sB1r = (float*)(sW2i + SM_W_H);
    float* sB1i = sB1r + 128;
    float* sB2r = sB1i + 128;
    float* sB2i = sB2r + 128;

    const int tid  = threadIdx.x;
    const int lane = tid & 31;
    const int wid  = tid >> 5;           // 0..15
    const int blk  = blockIdx.y;
    const int m0   = blockIdx.x * 64;

    // ---- stage X, W1, W2, biases ----
    const __nv_bfloat16* gXr = Xr + ((size_t)blk * ROWS + m0) * BLKW;
    const __nv_bfloat16* gXi = Xi + ((size_t)blk * ROWS + m0) * BLKW;
    const size_t wbase = (size_t)blk * BLKW * BLKW;
    #pragma unroll
    for (int it = 0; it < 2; it++) {
        int idx = tid + it * 512;                // 0..1023 (64 rows x 16 chunks)
        int row = idx >> 4, c = idx & 15;
        *(uint4*)(sXr + row * KPAD + c * 8) = *(const uint4*)(gXr + row * BLKW + c * 8);
        *(uint4*)(sXi + row * KPAD + c * 8) = *(const uint4*)(gXi + row * BLKW + c * 8);
    }
    #pragma unroll
    for (int it = 0; it < 4; it++) {
        int idx = tid + it * 512;                // 0..2047 (128 rows x 16 chunks)
        int row = idx >> 4, c = idx & 15;
        *(uint4*)(sW1r + row * KPAD + c * 8) = *(const uint4*)(W1r + wbase + row * BLKW + c * 8);
        *(uint4*)(sW1i + row * KPAD + c * 8) = *(const uint4*)(W1i + wbase + row * BLKW + c * 8);
        *(uint4*)(sW2r + row * KPAD + c * 8) = *(const uint4*)(W2r + wbase + row * BLKW + c * 8);
        *(uint4*)(sW2i + row * KPAD + c * 8) = *(const uint4*)(W2i + wbase + row * BLKW + c * 8);
    }
    if (tid < BLKW) {
        sB1r[tid] = B1[blk * BLKW + tid];
        sB1i[tid] = B1[NB * BLKW + blk * BLKW + tid];
        sB2r[tid] = B2[blk * BLKW + tid];
        sB2i[tid] = B2[NB * BLKW + blk * BLKW + tid];
    }
    __syncthreads();

    const int wm = wid & 3;      // 16-row group
    const int wn = wid >> 2;     // 32-col group
    const int n_base = wn * 32;

    const int grp = lane >> 3;
    const int rA  = wm * 16 + (lane & 7) + ((grp & 1) << 3);
    const int kA  = (grp >> 1) << 3;
    const uint32_t offA = (uint32_t)(rA * KPAD + kA) * 2;
    const uint32_t offB = (uint32_t)((lane & 7) * KPAD + ((lane >> 3) & 1) * 8) * 2;

    const uint32_t baseXr  = smem_u32(sXr),  baseXi  = smem_u32(sXi);
    const uint32_t baseO1r = smem_u32(sO1r), baseO1i = smem_u32(sO1i);
    const uint32_t baseW1r = smem_u32(sW1r), baseW1i = smem_u32(sW1i);
    const uint32_t baseW2r = smem_u32(sW2r), baseW2i = smem_u32(sW2i);

    float accR[4][4], accI[4][4];

    // ================= layer 1: o1 = relu(X*W1 + b1) -> smem =================
    complex_gemm_layer(baseXr, baseXi, baseW1r, baseW1i, offA, offB, n_base, accR, accI);

    #pragma unroll
    for (int ni = 0; ni < 4; ni++) {
        const int col = n_base + ni * 8 + (lane & 3) * 2;
        const int row = wm * 16 + (lane >> 2);
        const float br0 = sB1r[col], br1 = sB1r[col + 1];
        const float bi0 = sB1i[col], bi1 = sB1i[col + 1];
        #pragma unroll
        for (int half = 0; half < 2; half++) {
            const int q0 = half * 2, q1 = half * 2 + 1;
            float vr0 = fmaxf(accR[ni][q0] + br0, 0.0f);
            float vr1 = fmaxf(accR[ni][q1] + br1, 0.0f);
            float vi0 = fmaxf(accI[ni][q0] + bi0, 0.0f);
            float vi1 = fmaxf(accI[ni][q1] + bi1, 0.0f);
            const int so = (row + half * 8) * KPAD + col;
            *(__nv_bfloat162*)(sO1r + so) = __floats2bfloat162_rn(vr0, vr1);
            *(__nv_bfloat162*)(sO1i + so) = __floats2bfloat162_rn(vi0, vi1);
        }
    }
    __syncthreads();

    // ================= layer 2: o2 = softshrink(o1*W2 + b2) -> gmem ==========
    complex_gemm_layer(baseO1r, baseO1i, baseW2r, baseW2i, offA, offB, n_base, accR, accI);

    #pragma unroll
    for (int ni = 0; ni < 4; ni++) {
        const int col = n_base + ni * 8 + (lane & 3) * 2;
        const int row = m0 + wm * 16 + (lane >> 2);
        const float br0 = sB2r[col], br1 = sB2r[col + 1];
        const float bi0 = sB2i[col], bi1 = sB2i[col + 1];
        #pragma unroll
        for (int half = 0; half < 2; half++) {
            const int q0 = half * 2, q1 = half * 2 + 1;
            float vr0 = softshrink_f(accR[ni][q0] + br0);
            float vr1 = softshrink_f(accR[ni][q1] + br1);
            float vi0 = softshrink_f(accI[ni][q0] + bi0);
            float vi1 = softshrink_f(accI[ni][q1] + bi1);
            const size_t g = ((size_t)blk * ROWS + row + half * 8) * BLKW + col;
            *(__nv_bfloat162*)(Or + g) = __floats2bfloat162_rn(vr0, vr1);
            *(__nv_bfloat162*)(Oi + g) = __floats2bfloat162_rn(vi0, vi1);
        }
    }
}

// -----------------------------------------------------------------------------
extern "C" void kernel_launch(void* const* d_in, const int* in_sizes, int n_in,
                              void* d_out, int out_size) {
    (void)in_sizes; (void)n_in; (void)out_size;
    const float* x  = (const float*)d_in[0];
    const float* w1 = (const float*)d_in[1];
    const float* b1 = (const float*)d_in[2];
    const float* w2 = (const float*)d_in[3];
    const float* b2 = (const float*)d_in[4];
    float* out = (float*)d_out;

    __nv_bfloat16 *xr, *xi, *w1r, *w1i, *w2r, *w2i;
    float *gtwr, *gtwi;
    cudaGetSymbolAddress((void**)&xr,  g_xr);
    cudaGetSymbolAddress((void**)&xi,  g_xi);
    cudaGetSymbolAddress((void**)&w1r, g_w1r);
    cudaGetSymbolAddress((void**)&w1i, g_w1i);
    cudaGetSymbolAddress((void**)&w2r, g_w2r);
    cudaGetSymbolAddress((void**)&w2i, g_w2i);
    cudaGetSymbolAddress((void**)&gtwr, g_gtwr);
    cudaGetSymbolAddress((void**)&gtwi, g_gtwi);

    cudaFuncSetAttribute(fused_mlp_kernel,
                         cudaFuncAttributeMaxDynamicSharedMemorySize, SM_BYTES);

    setup_twiddles<<<4, 256>>>(gtwr, gtwi);
    convert_weights<<<(NB * BLKW * BLKW + 255) / 256, 256>>>(w1, w2, w1r, w1i, w2r, w2i);

    fft_fwd_kernel<<<ROWS / 2, 256>>>(x, xr, xi, gtwr, gtwi);

    dim3 grid(ROWS / 64, NB);
    fused_mlp_kernel<<<grid, 512, SM_BYTES>>>(xr, xi, w1r, w1i, w2r, w2i, b1, b2, xr, xi);

    fft_inv_kernel<<<ROWS / 2, 256>>>(xr, xi, x, out, gtwr, gtwi);
}

// round 8
// speedup vs baseline: 1.1359x; 1.0734x over previous
#include <cuda_runtime.h>
#include <cuda_bf16.h>
#include <math.h>
#include <stdint.h>

#define ROWS      32768
#define CCH       1024
#define NB        8
#define BLKW      128
#define KPAD      136            // padded halves per smem row (272 B)
#define LAMBDA_F  0.01f
#define INV_SQRTC (1.0f / 32.0f)

// ------------------------- scratch (device globals) -------------------------
__device__ __align__(128) __nv_bfloat16 g_xr [(size_t)NB * ROWS * BLKW]; // blocked [blk][row][128]
__device__ __align__(128) __nv_bfloat16 g_xi [(size_t)NB * ROWS * BLKW];
__device__ __align__(128) __nv_bfloat16 g_w1r[NB * BLKW * BLKW];
__device__ __align__(128) __nv_bfloat16 g_w1i[NB * BLKW * BLKW];
__device__ __align__(128) __nv_bfloat16 g_w2r[NB * BLKW * BLKW];
__device__ __align__(128) __nv_bfloat16 g_w2i[NB * BLKW * BLKW];
__device__ float2 g_tw[CCH];

// ------------------------- setup kernels -------------------------------------
__global__ void setup_twiddles(float2* tw) {
    int i = blockIdx.x * blockDim.x + threadIdx.x;
    if (i < CCH) {
        float s, c;
        sincosf(-6.283185307179586f * (float)i / (float)CCH, &s, &c);
        tw[i] = make_float2(c, s);
    }
}

__global__ void convert_weights(const float* __restrict__ w1,
                                const float* __restrict__ w2,
                                __nv_bfloat16* __restrict__ W1r, __nv_bfloat16* __restrict__ W1i,
                                __nv_bfloat16* __restrict__ W2r, __nv_bfloat16* __restrict__ W2i) {
    int idx = blockIdx.x * blockDim.x + threadIdx.x;   // dst layout [blk][n][k]
    if (idx >= NB * BLKW * BLKW) return;
    int blk = idx >> 14;
    int n   = (idx >> 7) & 127;
    int k   = idx & 127;
    size_t src = (size_t)blk * (BLKW * BLKW) + (size_t)k * BLKW + n;  // w[.][blk][k][n]
    W1r[idx] = __float2bfloat16(w1[src]);
    W1i[idx] = __float2bfloat16(w1[(size_t)NB * BLKW * BLKW + src]);
    W2r[idx] = __float2bfloat16(w2[src]);
    W2i[idx] = __float2bfloat16(w2[(size_t)NB * BLKW * BLKW + src]);
}

// ------------------------- radix-4 Stockham FFT (float2, fused stage 1) -------
// forward: two real rows packed into one complex FFT
__global__ __launch_bounds__(256) void fft_fwd_kernel(const float* __restrict__ x,
                                                      __nv_bfloat16* __restrict__ outr,
                                                      __nv_bfloat16* __restrict__ outi,
                                                      const float2* __restrict__ gtw) {
    __shared__ __align__(16) float2 A[CCH], B[CCH], TW[CCH];
    const int t = threadIdx.x;
    const size_t rowa = (size_t)blockIdx.x * 2;
    const float* xa = x + rowa * CCH;
    const float* xb = xa + CCH;

    #pragma unroll
    for (int q = 0; q < 4; q++) {
        int pos = t + 256 * q;
        A[pos] = make_float2(xa[pos], xb[pos]);
        TW[pos] = gtw[pos];
    }
    __syncthreads();

    // stage p=1: no twiddles; contiguous float4 stores (conflict-free)
    {
        float2 z0 = A[t], z1 = A[t + 256], z2 = A[t + 512], z3 = A[t + 768];
        float v0r = z0.x + z2.x, v0i = z0.y + z2.y;
        float v1r = z0.x - z2.x, v1i = z0.y - z2.y;
        float v2r = z1.x + z3.x, v2i = z1.y + z3.y;
        float v3r = z1.y - z3.y, v3i = z3.x - z1.x;   // -i*(z1-z3)
        *(float4*)&B[4 * t]     = make_float4(v0r + v2r, v0i + v2i, v1r + v3r, v1i + v3i);
        *(float4*)&B[4 * t + 2] = make_float4(v0r - v2r, v0i - v2i, v1r - v3r, v1i - v3i);
    }
    __syncthreads();

    float2 *pr = B, *qr = A;
    #pragma unroll
    for (int p = 4; p <= 256; p <<= 2) {
        const int k = t & (p - 1);
        const int j = ((t - k) << 2) + k;
        const int a1 = k * (256 / p);
        float2 z0 = pr[t], z1 = pr[t + 256], z2 = pr[t + 512], z3 = pr[t + 768];
        float2 w1 = TW[a1], w2 = TW[2 * a1], w3 = TW[3 * a1];
        float u1r = z1.x * w1.x - z1.y * w1.y, u1i = z1.x * w1.y + z1.y * w1.x;
        float u2r = z2.x * w2.x - z2.y * w2.y, u2i = z2.x * w2.y + z2.y * w2.x;
        float u3r = z3.x * w3.x - z3.y * w3.y, u3i = z3.x * w3.y + z3.y * w3.x;
        float v0r = z0.x + u2r, v0i = z0.y + u2i;
        float v1r = z0.x - u2r, v1i = z0.y - u2i;
        float v2r = u1r + u3r, v2i = u1i + u3i;
        float v3r = u1i - u3i, v3i = u3r - u1r;    // -i*(u1-u3)
        qr[j]         = make_float2(v0r + v2r, v0i + v2i);
        qr[j + p]     = make_float2(v1r + v3r, v1i + v3i);
        qr[j + 2 * p] = make_float2(v0r - v2r, v0i - v2i);
        qr[j + 3 * p] = make_float2(v1r - v3r, v1i - v3i);
        __syncthreads();
        float2* tp = pr; pr = qr; qr = tp;
    }
    // final data in pr (== B)

    const float HS = 0.5f * INV_SQRTC;
    #pragma unroll
    for (int q = 0; q < 4; q++) {
        int pos = t + 256 * q;
        int nk = (CCH - pos) & (CCH - 1);
        float2 Z = pr[pos], W = pr[nk];
        float Ar = HS * (Z.x + W.x), Ai = HS * (Z.y - W.y);
        float Br = HS * (Z.y + W.y), Bi = HS * (W.x - Z.x);
        int blk = pos >> 7, col = pos & 127;
        size_t ga = ((size_t)blk * ROWS + rowa) * BLKW + col;
        outr[ga] = __float2bfloat16(Ar);
        outi[ga] = __float2bfloat16(Ai);
        outr[ga + BLKW] = __float2bfloat16(Br);
        outi[ga + BLKW] = __float2bfloat16(Bi);
    }
}

// inverse: Hermitian-symmetrize two spectra, pack, one IFFT -> two real rows
__global__ __launch_bounds__(256) void fft_inv_kernel(const __nv_bfloat16* __restrict__ inr,
                                                      const __nv_bfloat16* __restrict__ ini,
                                                      const float* __restrict__ xres,
                                                      float* __restrict__ out,
                                                      const float2* __restrict__ gtw) {
    __shared__ __align__(16) float2 YA[CCH], YB[CCH], A[CCH], TW[CCH];
    const int t = threadIdx.x;
    const size_t rowa = (size_t)blockIdx.x * 2;

    #pragma unroll
    for (int q = 0; q < 4; q++) {
        int pos = t + 256 * q;
        int blk = pos >> 7, col = pos & 127;
        size_t ga = ((size_t)blk * ROWS + rowa) * BLKW + col;
        YA[pos] = make_float2(__bfloat162float(inr[ga]), __bfloat162float(ini[ga]));
        YB[pos] = make_float2(__bfloat162float(inr[ga + BLKW]), __bfloat162float(ini[ga + BLKW]));
        TW[pos] = gtw[pos];
    }
    __syncthreads();

    // A = Herm(Ya) + i*Herm(Yb), ortho scale folded
    const float HS = 0.5f * INV_SQRTC;
    #pragma unroll
    for (int q = 0; q < 4; q++) {
        int pos = t + 256 * q;
        int nk = (CCH - pos) & (CCH - 1);
        float2 za = YA[pos], zan = YA[nk];
        float2 zb = YB[pos], zbn = YB[nk];
        float Ar = HS * (za.x + zan.x);
        float Ai = HS * (za.y - zan.y);
        float Br = HS * (zb.x + zbn.x);
        float Bi = HS * (zb.y - zbn.y);
        A[pos] = make_float2(Ar - Bi, Ai + Br);
    }
    __syncthreads();

    // stage p=1 (inverse: +i), float4 stores
    {
        float2 z0 = A[t], z1 = A[t + 256], z2 = A[t + 512], z3 = A[t + 768];
        float v0r = z0.x + z2.x, v0i = z0.y + z2.y;
        float v1r = z0.x - z2.x, v1i = z0.y - z2.y;
        float v2r = z1.x + z3.x, v2i = z1.y + z3.y;
        float v3r = z3.y - z1.y, v3i = z1.x - z3.x;   // +i*(z1-z3)
        *(float4*)&YA[4 * t]     = make_float4(v0r + v2r, v0i + v2i, v1r + v3r, v1i + v3i);
        *(float4*)&YA[4 * t + 2] = make_float4(v0r - v2r, v0i - v2i, v1r - v3r, v1i - v3i);
    }
    __syncthreads();

    float2 *pr = YA, *qr = A;
    #pragma unroll
    for (int p = 4; p <= 256; p <<= 2) {
        const int k = t & (p - 1);
        const int j = ((t - k) << 2) + k;
        const int a1 = k * (256 / p);
        float2 z0 = pr[t], z1 = pr[t + 256], z2 = pr[t + 512], z3 = pr[t + 768];
        float2 w1 = TW[a1], w2 = TW[2 * a1], w3 = TW[3 * a1];
        // conj twiddles
        float u1r = z1.x * w1.x + z1.y * w1.y, u1i = z1.y * w1.x - z1.x * w1.y;
        float u2r = z2.x * w2.x + z2.y * w2.y, u2i = z2.y * w2.x - z2.x * w2.y;
        float u3r = z3.x * w3.x + z3.y * w3.y, u3i = z3.y * w3.x - z3.x * w3.y;
        float v0r = z0.x + u2r, v0i = z0.y + u2i;
        float v1r = z0.x - u2r, v1i = z0.y - u2i;
        float v2r = u1r + u3r, v2i = u1i + u3i;
        float v3r = u3i - u1i, v3i = u1r - u3r;    // +i*(u1-u3)
        qr[j]         = make_float2(v0r + v2r, v0i + v2i);
        qr[j + p]     = make_float2(v1r + v3r, v1i + v3i);
        qr[j + 2 * p] = make_float2(v0r - v2r, v0i - v2i);
        qr[j + 3 * p] = make_float2(v1r - v3r, v1i - v3i);
        __syncthreads();
        float2* tp = pr; pr = qr; qr = tp;
    }
    // final data in pr (== YA)

    #pragma unroll
    for (int q = 0; q < 4; q++) {
        int pos = t + 256 * q;
        size_t ga = rowa * CCH + pos;
        float2 v = pr[pos];
        out[ga]       = v.x + xres[ga];
        out[ga + CCH] = v.y + xres[ga + CCH];
    }
}

// ------------------------- fused 2-layer HMMA MLP (persistent tiles) ----------
__device__ __forceinline__ float softshrink_f(float v) {
    return (v > LAMBDA_F) ? (v - LAMBDA_F) : ((v < -LAMBDA_F) ? (v + LAMBDA_F) : 0.0f);
}
__device__ __forceinline__ uint32_t smem_u32(const void* p) {
    uint32_t a;
    asm("{ .reg .u64 t; cvta.to.shared.u64 t, %1; cvt.u32.u64 %0, t; }" : "=r"(a) : "l"(p));
    return a;
}
__device__ __forceinline__ void mma16816(float* d, const uint32_t* a, const uint32_t* b) {
    asm volatile(
        "mma.sync.aligned.m16n8k16.row.col.f32.bf16.bf16.f32 "
        "{%0,%1,%2,%3}, {%4,%5,%6,%7}, {%8,%9}, {%0,%1,%2,%3};"
        : "+f"(d[0]), "+f"(d[1]), "+f"(d[2]), "+f"(d[3])
        : "r"(a[0]), "r"(a[1]), "r"(a[2]), "r"(a[3]), "r"(b[0]), "r"(b[1]));
}
__device__ __forceinline__ void ldm_x4(uint32_t* r, uint32_t addr) {
    asm volatile("ldmatrix.sync.aligned.m8n8.x4.shared.b16 {%0,%1,%2,%3}, [%4];"
        : "=r"(r[0]), "=r"(r[1]), "=r"(r[2]), "=r"(r[3]) : "r"(addr));
}
__device__ __forceinline__ void ldm_x2(uint32_t* r, uint32_t addr) {
    asm volatile("ldmatrix.sync.aligned.m8n8.x2.shared.b16 {%0,%1}, [%2];"
        : "=r"(r[0]), "=r"(r[1]) : "r"(addr));
}

__device__ __forceinline__ void complex_gemm_layer(
        uint32_t baseAr, uint32_t baseAi, uint32_t baseWr, uint32_t baseWi,
        uint32_t offA, uint32_t offB, int n_base,
        float accR[4][4], float accI[4][4]) {
    #pragma unroll
    for (int ni = 0; ni < 4; ni++)
        #pragma unroll
        for (int q = 0; q < 4; q++) { accR[ni][q] = 0.0f; accI[ni][q] = 0.0f; }

    #pragma unroll
    for (int ks = 0; ks < 8; ks++) {
        const uint32_t kb = (uint32_t)(ks * 16) * 2;
        uint32_t axr[4], axi[4], axni[4];
        ldm_x4(axr, baseAr + offA + kb);
        ldm_x4(axi, baseAi + offA + kb);
        #pragma unroll
        for (int q = 0; q < 4; q++) axni[q] = axi[q] ^ 0x80008000u;

        uint32_t bwr[4][2], bwi[4][2];
        #pragma unroll
        for (int ni = 0; ni < 4; ni++) {
            const uint32_t nb = (uint32_t)((n_base + ni * 8) * KPAD) * 2;
            ldm_x2(bwr[ni], baseWr + nb + offB + kb);
            ldm_x2(bwi[ni], baseWi + nb + offB + kb);
        }
        #pragma unroll
        for (int ni = 0; ni < 4; ni++) {
            mma16816(accR[ni], axr,  bwr[ni]);   // + Ar*Wr
            mma16816(accR[ni], axni, bwi[ni]);   // - Ai*Wi
            mma16816(accI[ni], axi,  bwr[ni]);   // + Ai*Wr
            mma16816(accI[ni], axr,  bwi[ni]);   // + Ar*Wi
        }
    }
}

// grid (128, NB), 512 threads (16 warps, 4x4), 1 CTA/SM; each CTA does 4 m-tiles.
#define TILES_PER_CTA 4
#define SM_X_H    (64 * KPAD)
#define SM_W_H    (128 * KPAD)
#define SM_BYTES  ((4 * SM_X_H + 4 * SM_W_H) * 2 + 4 * 128 * 4)

__global__ __launch_bounds__(512, 1) void fused_mlp_kernel(
        const __nv_bfloat16* __restrict__ Xr, const __nv_bfloat16* __restrict__ Xi,
        const __nv_bfloat16* __restrict__ W1r, const __nv_bfloat16* __restrict__ W1i,
        const __nv_bfloat16* __restrict__ W2r, const __nv_bfloat16* __restrict__ W2i,
        const float* __restrict__ B1, const float* __restrict__ B2,
        __nv_bfloat16* __restrict__ Or, __nv_bfloat16* __restrict__ Oi) {
    extern __shared__ __nv_bfloat16 sm[];
    __nv_bfloat16* sXr  = sm;
    __nv_bfloat16* sXi  = sXr + SM_X_H;
    __nv_bfloat16* sO1r = sXi + SM_X_H;
    __nv_bfloat16* sO1i = sO1r + SM_X_H;
    __nv_bfloat16* sW1r = sO1i + SM_X_H;
    __nv_bfloat16* sW1i = sW1r + SM_W_H;
    __nv_bfloat16* sW2r = sW1i + SM_W_H;
    __nv_bfloat16* sW2i = sW2r + SM_W_H;
    float* sB1r = (float*)(sW2i + SM_W_H);
    float* sB1i = sB1r + 128;
    float* sB2r = sB1i + 128;
    float* sB2i = sB2r + 128;

    const int tid  = threadIdx.x;
    const int lane = tid & 31;
    const int wid  = tid >> 5;           // 0..15
    const int blk  = blockIdx.y;

    // ---- stage weights + biases ONCE ----
    const size_t wbase = (size_t)blk * BLKW * BLKW;
    #pragma unroll
    for (int it = 0; it < 4; it++) {
        int idx = tid + it * 512;                // 0..2047 (128 rows x 16 chunks)
        int row = idx >> 4, c = idx & 15;
        *(uint4*)(sW1r + row * KPAD + c * 8) = *(const uint4*)(W1r + wbase + row * BLKW + c * 8);
        *(uint4*)(sW1i + row * KPAD + c * 8) = *(const uint4*)(W1i + wbase + row * BLKW + c * 8);
        *(uint4*)(sW2r + row * KPAD + c * 8) = *(const uint4*)(W2r + wbase + row * BLKW + c * 8);
        *(uint4*)(sW2i + row * KPAD + c * 8) = *(const uint4*)(W2i + wbase + row * BLKW + c * 8);
    }
    if (tid < BLKW) {
        sB1r[tid] = B1[blk * BLKW + tid];
        sB1i[tid] = B1[NB * BLKW + blk * BLKW + tid];
        sB2r[tid] = B2[blk * BLKW + tid];
        sB2i[tid] = B2[NB * BLKW + blk * BLKW + tid];
    }

    const int wm = wid & 3;      // 16-row group
    const int wn = wid >> 2;     // 32-col group
    const int n_base = wn * 32;

    const int grp = lane >> 3;
    const int rA  = wm * 16 + (lane & 7) + ((grp & 1) << 3);
    const int kA  = (grp >> 1) << 3;
    const uint32_t offA = (uint32_t)(rA * KPAD + kA) * 2;
    const uint32_t offB = (uint32_t)((lane & 7) * KPAD + ((lane >> 3) & 1) * 8) * 2;

    const uint32_t baseXr  = smem_u32(sXr),  baseXi  = smem_u32(sXi);
    const uint32_t baseO1r = smem_u32(sO1r), baseO1i = smem_u32(sO1i);
    const uint32_t baseW1r = smem_u32(sW1r), baseW1i = smem_u32(sW1i);
    const uint32_t baseW2r = smem_u32(sW2r), baseW2i = smem_u32(sW2i);

    float accR[4][4], accI[4][4];

    for (int tile = 0; tile < TILES_PER_CTA; tile++) {
        const int m0 = (blockIdx.x * TILES_PER_CTA + tile) * 64;

        // ---- stage X tile ----
        const __nv_bfloat16* gXr = Xr + ((size_t)blk * ROWS + m0) * BLKW;
        const __nv_bfloat16* gXi = Xi + ((size_t)blk * ROWS + m0) * BLKW;
        #pragma unroll
        for (int it = 0; it < 2; it++) {
            int idx = tid + it * 512;            // 0..1023 (64 rows x 16 chunks)
            int row = idx >> 4, c = idx & 15;
            *(uint4*)(sXr + row * KPAD + c * 8) = *(const uint4*)(gXr + row * BLKW + c * 8);
            *(uint4*)(sXi + row * KPAD + c * 8) = *(const uint4*)(gXi + row * BLKW + c * 8);
        }
        __syncthreads();

        // ===== layer 1: o1 = relu(X*W1 + b1) -> smem =====
        complex_gemm_layer(baseXr, baseXi, baseW1r, baseW1i, offA, offB, n_base, accR, accI);

        #pragma unroll
        for (int ni = 0; ni < 4; ni++) {
            const int col = n_base + ni * 8 + (lane & 3) * 2;
            const int row = wm * 16 + (lane >> 2);
            const float br0 = sB1r[col], br1 = sB1r[col + 1];
            const float bi0 = sB1i[col], bi1 = sB1i[col + 1];
            #pragma unroll
            for (int half = 0; half < 2; half++) {
                const int q0 = half * 2, q1 = half * 2 + 1;
                float vr0 = fmaxf(accR[ni][q0] + br0, 0.0f);
                float vr1 = fmaxf(accR[ni][q1] + br1, 0.0f);
                float vi0 = fmaxf(accI[ni][q0] + bi0, 0.0f);
                float vi1 = fmaxf(accI[ni][q1] + bi1, 0.0f);
                const int so = (row + half * 8) * KPAD + col;
                *(__nv_bfloat162*)(sO1r + so) = __floats2bfloat162_rn(vr0, vr1);
                *(__nv_bfloat162*)(sO1i + so) = __floats2bfloat162_rn(vi0, vi1);
            }
        }
        __syncthreads();

        // ===== layer 2: o2 = softshrink(o1*W2 + b2) -> gmem =====
        complex_gemm_layer(baseO1r, baseO1i, baseW2r, baseW2i, offA, offB, n_base, accR, accI);

        #pragma unroll
        for (int ni = 0; ni < 4; ni++) {
            const int col = n_base + ni * 8 + (lane & 3) * 2;
            const int row = m0 + wm * 16 + (lane >> 2);
            const float br0 = sB2r[col], br1 = sB2r[col + 1];
            const float bi0 = sB2i[col], bi1 = sB2i[col + 1];
            #pragma unroll
            for (int half = 0; half < 2; half++) {
                const int q0 = half * 2, q1 = half * 2 + 1;
                float vr0 = softshrink_f(accR[ni][q0] + br0);
                float vr1 = softshrink_f(accR[ni][q1] + br1);
                float vi0 = softshrink_f(accI[ni][q0] + bi0);
                float vi1 = softshrink_f(accI[ni][q1] + bi1);
                const size_t g = ((size_t)blk * ROWS + row + half * 8) * BLKW + col;
                *(__nv_bfloat162*)(Or + g) = __floats2bfloat162_rn(vr0, vr1);
                *(__nv_bfloat162*)(Oi + g) = __floats2bfloat162_rn(vi0, vi1);
            }
        }
    }
}

// -----------------------------------------------------------------------------
extern "C" void kernel_launch(void* const* d_in, const int* in_sizes, int n_in,
                              void* d_out, int out_size) {
    (void)in_sizes; (void)n_in; (void)out_size;
    const float* x  = (const float*)d_in[0];
    const float* w1 = (const float*)d_in[1];
    const float* b1 = (const float*)d_in[2];
    const float* w2 = (const float*)d_in[3];
    const float* b2 = (const float*)d_in[4];
    float* out = (float*)d_out;

    __nv_bfloat16 *xr, *xi, *w1r, *w1i, *w2r, *w2i;
    float2 *gtw;
    cudaGetSymbolAddress((void**)&xr,  g_xr);
    cudaGetSymbolAddress((void**)&xi,  g_xi);
    cudaGetSymbolAddress((void**)&w1r, g_w1r);
    cudaGetSymbolAddress((void**)&w1i, g_w1i);
    cudaGetSymbolAddress((void**)&w2r, g_w2r);
    cudaGetSymbolAddress((void**)&w2i, g_w2i);
    cudaGetSymbolAddress((void**)&gtw, g_tw);

    cudaFuncSetAttribute(fused_mlp_kernel,
                         cudaFuncAttributeMaxDynamicSharedMemorySize, SM_BYTES);

    setup_twiddles<<<4, 256>>>(gtw);
    convert_weights<<<(NB * BLKW * BLKW + 255) / 256, 256>>>(w1, w2, w1r, w1i, w2r, w2i);

    fft_fwd_kernel<<<ROWS / 2, 256>>>(x, xr, xi, gtw);

    dim3 grid(ROWS / 64 / TILES_PER_CTA, NB);
    fused_mlp_kernel<<<grid, 512, SM_BYTES>>>(xr, xi, w1r, w1i, w2r, w2i, b1, b2, xr, xi);

    fft_inv_kernel<<<ROWS / 2, 256>>>(xr, xi, x, out, gtw);
}